// round 5
// baseline (speedup 1.0000x reference)
#include <cuda_runtime.h>
#include <cuda_bf16.h>

#define NBINS 36
#define PS 32
#define WPC 8                 // warps (patches) per CTA
#define THREADS (WPC * 32)

#define TWO_PI_F 6.28318530717958647692f   // 0x40C90FDB
#define PI_F     3.14159265358979323846f   // 0x40490FDB
#define K_BIN    5.72957795130823208768f   // 36 / (2*pi)

__global__ void __launch_bounds__(THREADS)
orientation_kernel(const float* __restrict__ x,
                   const float* __restrict__ gxw,
                   const float* __restrict__ gyw,
                   const float* __restrict__ smw,
                   const float* __restrict__ gk,
                   float* __restrict__ out,
                   int B)
{
    __shared__ float gks[PS * PS];
    __shared__ float hist[WPC][NBINS];

    const int tid  = threadIdx.x;
    const int lane = tid & 31;
    const int w    = tid >> 5;
    const int patch = blockIdx.x * WPC + w;

    // Stage gk (4 KB) into shared, zero this warp's histogram.
    for (int i = tid; i < PS * PS; i += THREADS) gks[i] = gk[i];
    hist[w][lane] = 0.0f;
    if (lane < NBINS - 32) hist[w][lane + 32] = 0.0f;
    __syncthreads();

    if (patch >= B) return;   // whole warp exits together; no __syncthreads below

    const float g0 = __ldg(gxw + 0), g1 = __ldg(gxw + 1), g2 = __ldg(gxw + 2);
    const float h0 = __ldg(gyw + 0), h1 = __ldg(gyw + 1), h2 = __ldg(gyw + 2);

    const float* p = x + (size_t)patch * (PS * PS) + lane;
    const int sl = (lane > 0)  ? lane - 1 : 0;    // replicate-pad left
    const int sr = (lane < 31) ? lane + 1 : 31;   // replicate-pad right

    float cur = __ldg(p);     // row 0
    float prv = cur;          // replicate-pad top
    float* hrow = hist[w];

    #pragma unroll 4
    for (int r = 0; r < PS; ++r) {
        const float nxt = (r + 1 < PS) ? __ldg(p + (r + 1) * PS) : cur; // replicate-pad bottom
        const float lft = __shfl_sync(0xffffffffu, cur, sl);
        const float rgt = __shfl_sync(0xffffffffu, cur, sr);

        // Bit-exact gradients (separate mul/add, no FMA contraction — matches XLA)
        const float gx = __fadd_rn(__fadd_rn(__fmul_rn(g0, lft), __fmul_rn(g1, cur)),
                                   __fmul_rn(g2, rgt));
        const float gy = __fadd_rn(__fadd_rn(__fmul_rn(h0, prv), __fmul_rn(h1, cur)),
                                   __fmul_rn(h2, nxt));

        const float m2  = __fadd_rn(__fadd_rn(__fmul_rn(gx, gx), __fmul_rn(gy, gy)), 1e-10f);
        const float mag = __fmul_rn(__fsqrt_rn(m2), gks[r * PS + lane]);

        if (mag > 0.001f) {
            // ---- fast path: ob in "bin units" = K * mod(atan2(gy,gx), 2pi) ----
            const float ax = fabsf(gx), ay = fabsf(gy);
            const float mn = fminf(ax, ay), mx = fmaxf(ax, ay);
            const float rt = __fdividef(mn, mx);               // [0, 1]
            const bool red = rt > 0.4142135623730950f;         // tan(pi/8) reduction
            const float z  = red ? __fdividef(rt - 1.0f, rt + 1.0f) : rt;  // [-0.4142, 0.4142]
            const float s  = z * z;
            // Cephes atanf kernel, scaled so result is K*atan(z)
            float t = fmaf(8.05374449538e-2f, s, -1.38776856032e-1f);
            t = fmaf(t, s,  1.99777106478e-1f);
            t = fmaf(t, s, -3.33329491539e-1f);
            t = t * s;
            const float v = fmaf(K_BIN, t, K_BIN);             // K*(1 + t)
            float aU = fmaf(v, z, red ? 4.5f : 0.0f);          // K*atan(r) in [0, 4.5]
            if (ay > ax)    aU = 9.0f  - aU;                   // K*pi/2  = 9
            if (gx < 0.0f)  aU = 18.0f - aU;                   // K*pi    = 18
            const float ob_a = (gy < 0.0f) ? 36.0f - aU : aU;  // K*2pi   = 36

            const float bf_a = floorf(ob_a);
            const float fr_a = ob_a - bf_a;

            int bin; float wt;
            if (fr_a >= 1e-4f && fr_a <= 0.9999f) {
                bin = (int)bf_a;
                if (bin >= NBINS) bin -= NBINS;
                wt = (1.0f - fr_a) * mag;
            } else {
                // ---- exact fallback (bit-identical to reference) near bin edges ----
                const float ori = atan2f(gy, gx);
                const float rr  = (ori < 0.0f) ? __fadd_rn(ori, TWO_PI_F) : ori;
                const float ob  = __fdiv_rn(__fmul_rn(36.0f, rr), TWO_PI_F);
                const float bf  = floorf(ob);
                const float wo1 = __fsub_rn(ob, bf);
                wt  = __fmul_rn(__fsub_rn(1.0f, wo1), mag);
                bin = (int)bf;
                if (bin >= NBINS) bin -= NBINS;
            }
            atomicAdd(hrow + bin, wt);
        }
        prv = cur; cur = nxt;
    }
    __syncwarp();

    // ---- angular smoothing (zero-padded conv3) + first-index argmax ----
    const float s0 = __ldg(smw + 0), s1 = __ldg(smw + 1), s2 = __ldg(smw + 2);
    // hist/(H*W) skipped: exact power-of-2 scale, argmax-invariant.

    const float a1 = (lane > 0) ? hrow[lane - 1] : 0.0f;
    const float m1 = hrow[lane];
    const float c1 = hrow[lane + 1];                 // lane 31 -> bin 32, valid
    float v1 = __fadd_rn(__fadd_rn(__fmul_rn(s0, a1), __fmul_rn(s1, m1)),
                         __fmul_rn(s2, c1));

    float v2 = -1.0f;                                // hist >= 0 so never wins
    if (lane < 4) {
        const int b = lane + 32;
        const float a2 = hrow[b - 1];
        const float m2v = hrow[b];
        const float c2 = (b < NBINS - 1) ? hrow[b + 1] : 0.0f;
        v2 = __fadd_rn(__fadd_rn(__fmul_rn(s0, a2), __fmul_rn(s1, m2v)),
                       __fmul_rn(s2, c2));
    }

    float bv; int bi;
    if (v2 > v1) { bv = v2; bi = lane + 32; }
    else         { bv = v1; bi = lane; }

    #pragma unroll
    for (int off = 16; off > 0; off >>= 1) {
        const float ov = __shfl_xor_sync(0xffffffffu, bv, off);
        const int   oi = __shfl_xor_sync(0xffffffffu, bi, off);
        if (ov > bv || (ov == bv && oi < bi)) { bv = ov; bi = oi; }
    }

    if (lane == 0) {
        const float t = __fdiv_rn(__fmul_rn(TWO_PI_F, (float)bi), 36.0f);
        out[patch] = -__fsub_rn(t, PI_F);
    }
}

extern "C" void kernel_launch(void* const* d_in, const int* in_sizes, int n_in,
                              void* d_out, int out_size) {
    const float* x   = (const float*)d_in[0];
    const float* gxw = (const float*)d_in[1];
    const float* gyw = (const float*)d_in[2];
    const float* smw = (const float*)d_in[3];
    const float* gk  = (const float*)d_in[4];
    float* out = (float*)d_out;
    const int B = out_size;
    const int grid = (B + WPC - 1) / WPC;
    orientation_kernel<<<grid, THREADS>>>(x, gxw, gyw, smw, gk, out, B);
}

// round 6
// speedup vs baseline: 1.1526x; 1.1526x over previous
#include <cuda_runtime.h>
#include <cuda_bf16.h>

#define NBINS 36
#define PS 32
#define WPC 8                 // warps (patches) per CTA
#define THREADS (WPC * 32)

#define TWO_PI_F 6.28318530717958647692f   // 0x40C90FDB
#define PI_F     3.14159265358979323846f   // 0x40490FDB
#define K_BIN    5.72957795130823208768f   // 36 / (2*pi)
#define TAN_PI8  0.4142135623730950488f

__global__ void __launch_bounds__(THREADS, 7)   // cap regs at 36 -> 87.5% occ
orientation_kernel(const float* __restrict__ x,
                   const float* __restrict__ gxw,
                   const float* __restrict__ gyw,
                   const float* __restrict__ smw,
                   const float* __restrict__ gk,
                   float* __restrict__ out,
                   int B)
{
    __shared__ float gks[PS * PS];
    __shared__ float hist[WPC][NBINS];

    const int tid  = threadIdx.x;
    const int lane = tid & 31;
    const int w    = tid >> 5;
    const int patch = blockIdx.x * WPC + w;

    // Stage gk (4 KB) into shared, zero this warp's histogram.
    for (int i = tid; i < PS * PS; i += THREADS) gks[i] = gk[i];
    hist[w][lane] = 0.0f;
    if (lane < NBINS - 32) hist[w][lane + 32] = 0.0f;
    __syncthreads();

    if (patch >= B) return;   // whole warp exits together; no __syncthreads below

    const float g0 = __ldg(gxw + 0), g1 = __ldg(gxw + 1), g2 = __ldg(gxw + 2);
    const float h0 = __ldg(gyw + 0), h1 = __ldg(gyw + 1), h2 = __ldg(gyw + 2);

    const float* p = x + (size_t)patch * (PS * PS) + lane;
    const int sl = (lane > 0)  ? lane - 1 : 0;    // replicate-pad left
    const int sr = (lane < 31) ? lane + 1 : 31;   // replicate-pad right

    float cur = __ldg(p);     // row 0
    float prv = cur;          // replicate-pad top
    float* hrow = hist[w];

    #pragma unroll 4
    for (int r = 0; r < PS; ++r) {
        const float nxt = (r + 1 < PS) ? __ldg(p + (r + 1) * PS) : cur; // replicate-pad bottom
        const float lft = __shfl_sync(0xffffffffu, cur, sl);
        const float rgt = __shfl_sync(0xffffffffu, cur, sr);

        // Bit-exact gradients (separate mul/add, no FMA contraction — matches XLA)
        const float gx = __fadd_rn(__fadd_rn(__fmul_rn(g0, lft), __fmul_rn(g1, cur)),
                                   __fmul_rn(g2, rgt));
        const float gy = __fadd_rn(__fadd_rn(__fmul_rn(h0, prv), __fmul_rn(h1, cur)),
                                   __fmul_rn(h2, nxt));

        const float m2  = __fadd_rn(__fadd_rn(__fmul_rn(gx, gx), __fmul_rn(gy, gy)), 1e-10f);
        // mag via rsqrt: bin never depends on mag; mask flips move only ~1e-3-weight. Safe.
        const float mag = __fmul_rn(__fmul_rn(__frsqrt_rn(m2), m2), gks[r * PS + lane]);

        if (mag > 0.001f) {
            // ---- fast path: ob in "bin units" = K * mod(atan2(gy,gx), 2pi) ----
            const float ax = fabsf(gx), ay = fabsf(gy);
            const float mn = fminf(ax, ay), mx = fmaxf(ax, ay);
            // reduction predicate without dividing: mn/mx > tan(pi/8)  <=>  mn > tan(pi/8)*mx
            const bool red = mn > TAN_PI8 * mx;
            // single division: z = red ? (mn-mx)/(mn+mx) : mn/mx   (== Cephes (rt-1)/(rt+1))
            const float num = red ? (mn - mx) : mn;
            const float den = red ? (mn + mx) : mx;
            const float z   = __fdividef(num, den);            // |z| <= tan(pi/8)
            const float s   = z * z;
            // Cephes atanf kernel, scaled so result is K*atan(z)  (validated in R5)
            float t = fmaf(8.05374449538e-2f, s, -1.38776856032e-1f);
            t = fmaf(t, s,  1.99777106478e-1f);
            t = fmaf(t, s, -3.33329491539e-1f);
            t = t * s;
            const float v = fmaf(K_BIN, t, K_BIN);             // K*(1 + t)
            float aU = fmaf(v, z, red ? 4.5f : 0.0f);          // K*atan(mn/mx) in [0, 4.5]
            if (ay > ax)    aU = 9.0f  - aU;                   // K*pi/2  = 9
            if (gx < 0.0f)  aU = 18.0f - aU;                   // K*pi    = 18
            const float ob_a = (gy < 0.0f) ? 36.0f - aU : aU;  // K*2pi   = 36

            const float bf_a = floorf(ob_a);
            const float fr_a = ob_a - bf_a;

            int bin; float wt;
            if (fr_a >= 1e-4f && fr_a <= 0.9999f) {
                bin = (int)bf_a;
                if (bin >= NBINS) bin -= NBINS;
                wt = (1.0f - fr_a) * mag;
            } else {
                // ---- exact fallback (bit-identical to reference) near bin edges ----
                const float gxs = __fadd_rn(__fadd_rn(__fmul_rn(g0, lft), __fmul_rn(g1, cur)),
                                            __fmul_rn(g2, rgt));
                const float gys = __fadd_rn(__fadd_rn(__fmul_rn(h0, prv), __fmul_rn(h1, cur)),
                                            __fmul_rn(h2, nxt));
                const float m2s  = __fadd_rn(__fadd_rn(__fmul_rn(gxs, gxs), __fmul_rn(gys, gys)), 1e-10f);
                const float mags = __fmul_rn(__fsqrt_rn(m2s), gks[r * PS + lane]);
                const float ori = atan2f(gys, gxs);
                const float rr  = (ori < 0.0f) ? __fadd_rn(ori, TWO_PI_F) : ori;
                const float ob  = __fdiv_rn(__fmul_rn(36.0f, rr), TWO_PI_F);
                const float bf  = floorf(ob);
                const float wo1 = __fsub_rn(ob, bf);
                wt  = __fmul_rn(__fsub_rn(1.0f, wo1), mags);
                bin = (int)bf;
                if (bin >= NBINS) bin -= NBINS;
            }
            atomicAdd(hrow + bin, wt);
        }
        prv = cur; cur = nxt;
    }
    __syncwarp();

    // ---- angular smoothing (zero-padded conv3) + first-index argmax ----
    const float s0 = __ldg(smw + 0), s1 = __ldg(smw + 1), s2 = __ldg(smw + 2);
    // hist/(H*W) skipped: exact power-of-2 scale, argmax-invariant.

    const float a1 = (lane > 0) ? hrow[lane - 1] : 0.0f;
    const float m1 = hrow[lane];
    const float c1 = hrow[lane + 1];                 // lane 31 -> bin 32, valid
    float v1 = __fadd_rn(__fadd_rn(__fmul_rn(s0, a1), __fmul_rn(s1, m1)),
                         __fmul_rn(s2, c1));

    float v2 = -1.0f;                                // hist >= 0 so never wins
    if (lane < 4) {
        const int b = lane + 32;
        const float a2 = hrow[b - 1];
        const float m2v = hrow[b];
        const float c2 = (b < NBINS - 1) ? hrow[b + 1] : 0.0f;
        v2 = __fadd_rn(__fadd_rn(__fmul_rn(s0, a2), __fmul_rn(s1, m2v)),
                       __fmul_rn(s2, c2));
    }

    float bv; int bi;
    if (v2 > v1) { bv = v2; bi = lane + 32; }
    else         { bv = v1; bi = lane; }

    #pragma unroll
    for (int off = 16; off > 0; off >>= 1) {
        const float ov = __shfl_xor_sync(0xffffffffu, bv, off);
        const int   oi = __shfl_xor_sync(0xffffffffu, bi, off);
        if (ov > bv || (ov == bv && oi < bi)) { bv = ov; bi = oi; }
    }

    if (lane == 0) {
        const float t = __fdiv_rn(__fmul_rn(TWO_PI_F, (float)bi), 36.0f);
        out[patch] = -__fsub_rn(t, PI_F);
    }
}

extern "C" void kernel_launch(void* const* d_in, const int* in_sizes, int n_in,
                              void* d_out, int out_size) {
    const float* x   = (const float*)d_in[0];
    const float* gxw = (const float*)d_in[1];
    const float* gyw = (const float*)d_in[2];
    const float* smw = (const float*)d_in[3];
    const float* gk  = (const float*)d_in[4];
    float* out = (float*)d_out;
    const int B = out_size;
    const int grid = (B + WPC - 1) / WPC;
    orientation_kernel<<<grid, THREADS>>>(x, gxw, gyw, smw, gk, out, B);
}

// round 7
// speedup vs baseline: 1.3430x; 1.1652x over previous
#include <cuda_runtime.h>
#include <cuda_bf16.h>

#define NBINS 36
#define PS 32
#define WPC 8                 // warps (patches) per CTA
#define THREADS (WPC * 32)

#define TWO_PI_F 6.28318530717958647692f   // 0x40C90FDB
#define PI_F     3.14159265358979323846f   // 0x40490FDB
#define K_BIN    5.72957795130823208768f   // 36 / (2*pi)
#define TAN_PI8  0.4142135623730950488f

// One warp = one patch. Per-row body: branchless fast path, predicated atomic,
// warp-uniform rare fallback (bit-exact vs reference).
template<bool SIMPLE>
__device__ __forceinline__ void patch_hist(const float* __restrict__ p,
                                           const float* __restrict__ gks,
                                           float* __restrict__ hrow,
                                           float g0, float g1, float g2,
                                           float h0, float h1, float h2,
                                           int lane, int sl, int sr)
{
    float cur = __ldg(p);     // row 0
    float prv = cur;          // replicate-pad top

    #pragma unroll 8
    for (int r = 0; r < PS; ++r) {
        const float nxt = (r + 1 < PS) ? __ldg(p + (r + 1) * PS) : cur; // pad bottom
        const float lft = __shfl_sync(0xffffffffu, cur, sl);
        const float rgt = __shfl_sync(0xffffffffu, cur, sr);

        // Bit-exact gradients (no FMA contraction). SIMPLE: g1==h1==0 -> middle
        // term is +/-0 and fadd(a, +/-0)==a for all non-(-0) a (masked otherwise).
        float gx, gy;
        if (SIMPLE) {
            gx = __fadd_rn(__fmul_rn(g0, lft), __fmul_rn(g2, rgt));
            gy = __fadd_rn(__fmul_rn(h0, prv), __fmul_rn(h2, nxt));
        } else {
            gx = __fadd_rn(__fadd_rn(__fmul_rn(g0, lft), __fmul_rn(g1, cur)),
                           __fmul_rn(g2, rgt));
            gy = __fadd_rn(__fadd_rn(__fmul_rn(h0, prv), __fmul_rn(h1, cur)),
                           __fmul_rn(h2, nxt));
        }

        // Approx magnitude (validated: mask/weight insensitive at this scale)
        const float m2  = fmaf(gx, gx, fmaf(gy, gy, 1e-10f));
        const float mag = __frsqrt_rn(m2) * m2 * gks[r * PS + lane];
        const bool  valid = mag > 0.001f;

        // ---- branchless fast atan: ob in bin units = K * mod(atan2(gy,gx), 2pi)
        const float ax = fabsf(gx), ay = fabsf(gy);
        const float mn = fminf(ax, ay), mx = fmaxf(ax, ay);
        const bool  red = mn > TAN_PI8 * mx;          // mn/mx > tan(pi/8)
        const float num = red ? (mn - mx) : mn;       // Cephes (rt-1)/(rt+1) folded
        const float den = red ? (mn + mx) : mx;
        const float z   = __fdividef(num, den);       // |z| <= tan(pi/8)
        const float s   = z * z;
        float t = fmaf(8.05374449538e-2f, s, -1.38776856032e-1f);
        t = fmaf(t, s,  1.99777106478e-1f);
        t = fmaf(t, s, -3.33329491539e-1f);
        t = t * s;
        const float v = fmaf(K_BIN, t, K_BIN);        // K*(1 + t)
        float aU = fmaf(v, z, red ? 4.5f : 0.0f);     // K*atan(mn/mx) in [0, 4.5]
        if (ay > ax)    aU = 9.0f  - aU;              // K*pi/2  = 9
        if (gx < 0.0f)  aU = 18.0f - aU;              // K*pi    = 18
        const float ob = (gy < 0.0f) ? 36.0f - aU : aU;

        const float bf = floorf(ob);
        const float fr = ob - bf;
        int   bin = (int)bf;                          // <= 35 whenever fr >= 1e-4
        float wt  = (1.0f - fr) * mag;

        // Rare exact fallback near bin boundaries: warp-uniform branch (~0.6% taken)
        const bool nb = valid && (fabsf(fr - 0.5f) > 0.4999f);
        if (__any_sync(0xffffffffu, nb)) {
            if (nb) {
                const float m2s  = __fadd_rn(__fadd_rn(__fmul_rn(gx, gx),
                                                       __fmul_rn(gy, gy)), 1e-10f);
                const float mags = __fmul_rn(__fsqrt_rn(m2s), gks[r * PS + lane]);
                const float ori  = atan2f(gy, gx);
                const float rr   = (ori < 0.0f) ? __fadd_rn(ori, TWO_PI_F) : ori;
                const float obe  = __fdiv_rn(__fmul_rn(36.0f, rr), TWO_PI_F);
                const float bfe  = floorf(obe);
                const float wo1  = __fsub_rn(obe, bfe);
                wt  = __fmul_rn(__fsub_rn(1.0f, wo1), mags);
                bin = (int)bfe;
                if (bin >= NBINS) bin -= NBINS;
            }
        }

        if (valid) atomicAdd(hrow + bin, wt);         // short body -> predicated ATOMS

        prv = cur; cur = nxt;
    }
}

__global__ void __launch_bounds__(THREADS, 7)   // cap regs at 36 -> 87.5% occ
orientation_kernel(const float* __restrict__ x,
                   const float* __restrict__ gxw,
                   const float* __restrict__ gyw,
                   const float* __restrict__ smw,
                   const float* __restrict__ gk,
                   float* __restrict__ out,
                   int B)
{
    __shared__ float gks[PS * PS];
    __shared__ float hist[WPC][NBINS];

    const int tid  = threadIdx.x;
    const int lane = tid & 31;
    const int w    = tid >> 5;
    const int patch = blockIdx.x * WPC + w;

    for (int i = tid; i < PS * PS; i += THREADS) gks[i] = gk[i];
    hist[w][lane] = 0.0f;
    if (lane < NBINS - 32) hist[w][lane + 32] = 0.0f;
    __syncthreads();

    if (patch >= B) return;   // whole warp exits together; no __syncthreads below

    const float g0 = __ldg(gxw + 0), g1 = __ldg(gxw + 1), g2 = __ldg(gxw + 2);
    const float h0 = __ldg(gyw + 0), h1 = __ldg(gyw + 1), h2 = __ldg(gyw + 2);

    const float* p = x + (size_t)patch * (PS * PS) + lane;
    const int sl = (lane > 0)  ? lane - 1 : 0;    // replicate-pad left
    const int sr = (lane < 31) ? lane + 1 : 31;   // replicate-pad right
    float* hrow = hist[w];

    if (g1 == 0.0f && h1 == 0.0f)
        patch_hist<true >(p, gks, hrow, g0, g1, g2, h0, h1, h2, lane, sl, sr);
    else
        patch_hist<false>(p, gks, hrow, g0, g1, g2, h0, h1, h2, lane, sl, sr);

    __syncwarp();

    // ---- angular smoothing (zero-padded conv3) + first-index argmax ----
    const float s0 = __ldg(smw + 0), s1 = __ldg(smw + 1), s2 = __ldg(smw + 2);
    // hist/(H*W) skipped: exact power-of-2 scale, argmax-invariant.

    const float a1 = (lane > 0) ? hrow[lane - 1] : 0.0f;
    const float m1 = hrow[lane];
    const float c1 = hrow[lane + 1];                 // lane 31 -> bin 32, valid
    float v1 = __fadd_rn(__fadd_rn(__fmul_rn(s0, a1), __fmul_rn(s1, m1)),
                         __fmul_rn(s2, c1));

    float v2 = -1.0f;                                // hist >= 0 so never wins
    if (lane < 4) {
        const int b = lane + 32;
        const float a2 = hrow[b - 1];
        const float m2v = hrow[b];
        const float c2 = (b < NBINS - 1) ? hrow[b + 1] : 0.0f;
        v2 = __fadd_rn(__fadd_rn(__fmul_rn(s0, a2), __fmul_rn(s1, m2v)),
                       __fmul_rn(s2, c2));
    }

    float bv; int bi;
    if (v2 > v1) { bv = v2; bi = lane + 32; }
    else         { bv = v1; bi = lane; }

    #pragma unroll
    for (int off = 16; off > 0; off >>= 1) {
        const float ov = __shfl_xor_sync(0xffffffffu, bv, off);
        const int   oi = __shfl_xor_sync(0xffffffffu, bi, off);
        if (ov > bv || (ov == bv && oi < bi)) { bv = ov; bi = oi; }
    }

    if (lane == 0) {
        const float t = __fdiv_rn(__fmul_rn(TWO_PI_F, (float)bi), 36.0f);
        out[patch] = -__fsub_rn(t, PI_F);
    }
}

extern "C" void kernel_launch(void* const* d_in, const int* in_sizes, int n_in,
                              void* d_out, int out_size) {
    const float* x   = (const float*)d_in[0];
    const float* gxw = (const float*)d_in[1];
    const float* gyw = (const float*)d_in[2];
    const float* smw = (const float*)d_in[3];
    const float* gk  = (const float*)d_in[4];
    float* out = (float*)d_out;
    const int B = out_size;
    const int grid = (B + WPC - 1) / WPC;
    orientation_kernel<<<grid, THREADS>>>(x, gxw, gyw, smw, gk, out, B);
}

// round 11
// speedup vs baseline: 1.3798x; 1.0274x over previous
#include <cuda_runtime.h>
#include <cuda_bf16.h>

#define NBINS 36
#define PS 32
#define WPC 8                  // warps per CTA; each warp handles 2 patches
#define THREADS (WPC * 32)
#define PPW 2                  // patches per warp

#define TWO_PI_F 6.28318530717958647692f
#define PI_F     3.14159265358979323846f
#define K_BIN    5.72957795130823208768f   // 36 / (2*pi)
#define TAN_PI8  0.4142135623730950488f

struct PixOut { int bin; float wt; bool valid; bool nb; };

// Fast path for one pixel (R5-R7 validated numerics: Cephes atan, conditional
// reduction folded into a single division). Result in "bin units".
__device__ __forceinline__ PixOut pixel_fast(float gx, float gy, float gkv)
{
    PixOut o;
    const float m2  = fmaf(gx, gx, fmaf(gy, gy, 1e-10f));
    const float mag = __frsqrt_rn(m2) * m2 * gkv;
    o.valid = mag > 0.001f;

    const float ax = fabsf(gx), ay = fabsf(gy);
    const float mn = fminf(ax, ay), mx = fmaxf(ax, ay);
    const bool  red = mn > TAN_PI8 * mx;            // mn/mx > tan(pi/8)
    const float num = red ? (mn - mx) : mn;         // Cephes (rt-1)/(rt+1) folded
    const float den = red ? (mn + mx) : mx;
    const float z   = __fdividef(num, den);         // |z| <= tan(pi/8)
    const float s   = z * z;
    float t = fmaf(8.05374449538e-2f, s, -1.38776856032e-1f);
    t = fmaf(t, s,  1.99777106478e-1f);
    t = fmaf(t, s, -3.33329491539e-1f);
    t = t * s;
    const float v = fmaf(K_BIN, t, K_BIN);          // K*(1 + t)
    float aU = fmaf(v, z, red ? 4.5f : 0.0f);       // K*atan(mn/mx) in [0, 4.5]
    if (ay > ax)   aU = 9.0f  - aU;                 // K*pi/2
    if (gx < 0.0f) aU = 18.0f - aU;                 // K*pi
    const float ob = (gy < 0.0f) ? 36.0f - aU : aU; // K*2pi

    const float bf = floorf(ob);
    const float fr = ob - bf;
    o.bin = (int)bf;                                // <= 35 whenever fr >= 1e-4
    o.wt  = (1.0f - fr) * mag;
    // near-boundary: defer to bit-exact fallback (window 1e-4 per side,
    // poly error ~1.2e-6 bins -- validated bit-identical in R5/R6/R7)
    o.nb  = o.valid && (fabsf(fr - 0.5f) > 0.4999f);
    return o;
}

// Bit-exact reference path (atan2f + rn ops), used for rare boundary pixels.
__device__ __forceinline__ void pixel_exact(float gx, float gy, float gkv,
                                            int& bin, float& wt)
{
    const float m2s  = __fadd_rn(__fadd_rn(__fmul_rn(gx, gx), __fmul_rn(gy, gy)), 1e-10f);
    const float mags = __fmul_rn(__fsqrt_rn(m2s), gkv);
    const float ori  = atan2f(gy, gx);
    const float rr   = (ori < 0.0f) ? __fadd_rn(ori, TWO_PI_F) : ori;
    const float obe  = __fdiv_rn(__fmul_rn(36.0f, rr), TWO_PI_F);
    const float bfe  = floorf(obe);
    const float wo1  = __fsub_rn(obe, bfe);
    wt  = __fmul_rn(__fsub_rn(1.0f, wo1), mags);
    bin = (int)bfe;
    if (bin >= NBINS) bin -= NBINS;
}

template<bool SIMPLE>
__device__ __forceinline__ void patch_pair_hist(const float* __restrict__ p,
                                                const float2* __restrict__ gks2,
                                                float* __restrict__ hrow,
                                                float g0, float g1, float g2,
                                                float h0, float h1, float h2,
                                                int li, int lane, bool act)
{
    const int  sls = (li == 0)  ? lane : lane - 1;   // stays within half-warp
    const int  srs = (li == 15) ? lane : lane + 1;
    const bool pl0 = (li == 0), pl15 = (li == 15);

    float2 cur = __ldg((const float2*)p);            // row 0 (8B aligned)
    float2 prv = cur;                                // replicate-pad top

    #pragma unroll 4
    for (int r = 0; r < PS; ++r) {
        const float2 nxt = (r + 1 < PS) ? __ldg((const float2*)(p + (r + 1) * PS)) : cur;
        const float prevY = __shfl_sync(0xffffffffu, cur.y, sls);
        const float nextX = __shfl_sync(0xffffffffu, cur.x, srs);
        const float lftx = pl0  ? cur.x : prevY;     // left of col 2li (edge pad)
        const float rgty = pl15 ? cur.y : nextX;     // right of col 2li+1

        float gxa, gya, gxb, gyb;
        if (SIMPLE) {                                // g1==h1==0 (bit-equal, see R6/R7)
            gxa = __fadd_rn(__fmul_rn(g0, lftx),  __fmul_rn(g2, cur.y));
            gya = __fadd_rn(__fmul_rn(h0, prv.x), __fmul_rn(h2, nxt.x));
            gxb = __fadd_rn(__fmul_rn(g0, cur.x), __fmul_rn(g2, rgty));
            gyb = __fadd_rn(__fmul_rn(h0, prv.y), __fmul_rn(h2, nxt.y));
        } else {
            gxa = __fadd_rn(__fadd_rn(__fmul_rn(g0, lftx),  __fmul_rn(g1, cur.x)), __fmul_rn(g2, cur.y));
            gya = __fadd_rn(__fadd_rn(__fmul_rn(h0, prv.x), __fmul_rn(h1, cur.x)), __fmul_rn(h2, nxt.x));
            gxb = __fadd_rn(__fadd_rn(__fmul_rn(g0, cur.x), __fmul_rn(g1, cur.y)), __fmul_rn(g2, rgty));
            gyb = __fadd_rn(__fadd_rn(__fmul_rn(h0, prv.y), __fmul_rn(h1, cur.y)), __fmul_rn(h2, nxt.y));
        }

        const float2 gkv = gks2[r * 16 + li];
        PixOut a = pixel_fast(gxa, gya, gkv.x);
        PixOut b = pixel_fast(gxb, gyb, gkv.y);

        // rare exact fallback, warp-uniform entry (~1.3% of rows)
        if (__any_sync(0xffffffffu, a.nb || b.nb)) {
            if (a.nb) pixel_exact(gxa, gya, gkv.x, a.bin, a.wt);
            if (b.nb) pixel_exact(gxb, gyb, gkv.y, b.bin, b.wt);
        }

        if (act & a.valid) atomicAdd(hrow + a.bin, a.wt);
        if (act & b.valid) atomicAdd(hrow + b.bin, b.wt);

        prv = cur; cur = nxt;
    }
}

__global__ void __launch_bounds__(THREADS, 7)     // cap regs ~36 -> high occ
orientation_kernel(const float* __restrict__ x,
                   const float* __restrict__ gxw,
                   const float* __restrict__ gyw,
                   const float* __restrict__ smw,
                   const float* __restrict__ gk,
                   float* __restrict__ out,
                   int B)
{
    __shared__ float2 gks2[PS * PS / 2];
    __shared__ float  hist[WPC * PPW][NBINS];

    const int tid  = threadIdx.x;
    const int lane = tid & 31;
    const int w    = tid >> 5;
    const int h    = lane >> 4;            // half-warp -> which of 2 patches
    const int li   = lane & 15;            // covers columns 2li, 2li+1

    for (int i = tid; i < PS * PS / 2; i += THREADS)
        gks2[i] = ((const float2*)gk)[i];
    for (int i = tid; i < WPC * PPW * NBINS; i += THREADS)
        ((float*)hist)[i] = 0.0f;
    __syncthreads();

    const int patch = (blockIdx.x * WPC + w) * PPW + h;
    const bool act  = patch < B;

    const float g0 = __ldg(gxw + 0), g1 = __ldg(gxw + 1), g2 = __ldg(gxw + 2);
    const float h0 = __ldg(gyw + 0), h1 = __ldg(gyw + 1), h2 = __ldg(gyw + 2);

    const float* p = x + (act ? (size_t)patch * (PS * PS) : 0) + 2 * li;
    float* hrow = hist[w * PPW + h];

    if (g1 == 0.0f && h1 == 0.0f)
        patch_pair_hist<true >(p, gks2, hrow, g0, g1, g2, h0, h1, h2, li, lane, act);
    else
        patch_pair_hist<false>(p, gks2, hrow, g0, g1, g2, h0, h1, h2, li, lane, act);

    __syncwarp();   // warp w wrote only hists 2w and 2w+1

    // ---- smoothing (zero-pad conv3) + first-index argmax, once per patch ----
    const float s0 = __ldg(smw + 0), s1 = __ldg(smw + 1), s2 = __ldg(smw + 2);
    // hist/(H*W) skipped: exact power-of-2 scale, argmax-invariant.

    #pragma unroll
    for (int j = 0; j < PPW; ++j) {
        const float* hr = hist[w * PPW + j];

        const float a1 = (lane > 0) ? hr[lane - 1] : 0.0f;
        const float m1 = hr[lane];
        const float c1 = hr[lane + 1];               // lane 31 -> bin 32, valid
        float v1 = __fadd_rn(__fadd_rn(__fmul_rn(s0, a1), __fmul_rn(s1, m1)),
                             __fmul_rn(s2, c1));

        float v2 = -1.0f;                            // hist >= 0, never wins
        if (lane < 4) {
            const int b = lane + 32;
            const float a2 = hr[b - 1];
            const float m2v = hr[b];
            const float c2 = (b < NBINS - 1) ? hr[b + 1] : 0.0f;
            v2 = __fadd_rn(__fadd_rn(__fmul_rn(s0, a2), __fmul_rn(s1, m2v)),
                           __fmul_rn(s2, c2));
        }

        float bv; int bi;
        if (v2 > v1) { bv = v2; bi = lane + 32; }
        else         { bv = v1; bi = lane; }

        #pragma unroll
        for (int off = 16; off > 0; off >>= 1) {
            const float ov = __shfl_xor_sync(0xffffffffu, bv, off);
            const int   oi = __shfl_xor_sync(0xffffffffu, bi, off);
            if (ov > bv || (ov == bv && oi < bi)) { bv = ov; bi = oi; }
        }

        const int op = (blockIdx.x * WPC + w) * PPW + j;
        if (lane == 0 && op < B) {
            const float t = __fdiv_rn(__fmul_rn(TWO_PI_F, (float)bi), 36.0f);
            out[op] = -__fsub_rn(t, PI_F);
        }
    }
}

extern "C" void kernel_launch(void* const* d_in, const int* in_sizes, int n_in,
                              void* d_out, int out_size) {
    const float* x   = (const float*)d_in[0];
    const float* gxw = (const float*)d_in[1];
    const float* gyw = (const float*)d_in[2];
    const float* smw = (const float*)d_in[3];
    const float* gk  = (const float*)d_in[4];
    float* out = (float*)d_out;
    const int B = out_size;
    const int grid = (B + WPC * PPW - 1) / (WPC * PPW);
    orientation_kernel<<<grid, THREADS>>>(x, gxw, gyw, smw, gk, out, B);
}

// round 12
// speedup vs baseline: 1.7904x; 1.2976x over previous
#include <cuda_runtime.h>
#include <cuda_bf16.h>

#define NBINS 36
#define PS 32
#define WPC 8                  // warps per CTA; each warp handles 2 patches
#define THREADS (WPC * 32)
#define PPW 2                  // patches per warp

#define TWO_PI_F 6.28318530717958647692f
#define PI_F     3.14159265358979323846f
#define TAN_PI8  0.4142135623730950488f

// Cephes atanf coefficients pre-multiplied by K = 36/(2*pi) = 5.72957795...
// poly(s)*z ~= K*atan(z) for |z| <= tan(pi/8). Same relative accuracy as the
// validated R5-R11 path (~1.2e-6 bin units), only final-rounding differs.
#define KC9  0.46144556f      // K * 8.05374449538e-2
#define KC7 -0.79513296f      // K * -1.38776856032e-1
#define KC5  1.14463840f      // K * 1.99777106478e-1
#define KC3 -1.90983720f      // K * -3.33329491539e-1
#define KC1  5.72957795f      // K

struct PixOut { int bin; float wt; bool valid; bool nb; };

// Fast path for one pixel: Cephes atan (conditional reduction, single division),
// K folded into poly. Result in "bin units" ob in [-eps, 36+eps]; any edge
// spill has fr within 1e-4 of a boundary and is caught by nb -> exact fallback.
__device__ __forceinline__ PixOut pixel_fast(float gx, float gy, float gkv)
{
    PixOut o;
    const float m2 = fmaf(gx, gx, fmaf(gy, gy, 1e-10f));
    float rt;
    asm("sqrt.approx.f32 %0, %1;" : "=f"(rt) : "f"(m2));
    const float mag = rt * gkv;
    o.valid = mag > 0.001f;

    const float ax = fabsf(gx), ay = fabsf(gy);
    const float mn = fminf(ax, ay), mx = fmaxf(ax, ay);
    const bool  red = mn > TAN_PI8 * mx;            // mn/mx > tan(pi/8)
    const float num = red ? (mn - mx) : mn;         // Cephes (rt-1)/(rt+1) folded
    const float den = red ? (mn + mx) : mx;
    const float z   = __fdividef(num, den);         // |z| <= tan(pi/8)
    const float s   = z * z;
    float t = fmaf(KC9, s, KC7);
    t = fmaf(t, s, KC5);
    t = fmaf(t, s, KC3);
    t = fmaf(t, s, KC1);                            // t ~= K*atan(z)/z
    float aU = fmaf(t, z, red ? 4.5f : 0.0f);       // K*atan(mn/mx) in [0, 4.5]
    if (ay > ax)   aU = 9.0f  - aU;                 // K*pi/2
    if (gx < 0.0f) aU = 18.0f - aU;                 // K*pi
    const float ob = (gy < 0.0f) ? 36.0f - aU : aU; // K*2pi

    const float bf = floorf(ob);
    const float fr = ob - bf;
    o.bin = (int)bf;                                // in [0,35] whenever fr>=1e-4
    o.wt  = fmaf(-fr, mag, mag);                    // (1-fr)*mag up to 1 ulp
    // near-boundary (no valid gate: invalid lanes in fallback are harmless)
    o.nb  = fabsf(fr - 0.5f) > 0.4999f;             // window 1e-4 per side
    return o;
}

// Bit-exact reference path (atan2f + rn ops), used for rare boundary pixels.
__device__ __forceinline__ void pixel_exact(float gx, float gy, float gkv,
                                            int& bin, float& wt)
{
    const float m2s  = __fadd_rn(__fadd_rn(__fmul_rn(gx, gx), __fmul_rn(gy, gy)), 1e-10f);
    const float mags = __fmul_rn(__fsqrt_rn(m2s), gkv);
    const float ori  = atan2f(gy, gx);
    const float rr   = (ori < 0.0f) ? __fadd_rn(ori, TWO_PI_F) : ori;
    const float obe  = __fdiv_rn(__fmul_rn(36.0f, rr), TWO_PI_F);
    const float bfe  = floorf(obe);
    const float wo1  = __fsub_rn(obe, bfe);
    wt  = __fmul_rn(__fsub_rn(1.0f, wo1), mags);
    bin = (int)bfe;
    if (bin >= NBINS) bin -= NBINS;
}

// MODE: 0 = antisymmetric power-of-2 weights (gx = g0*(l-r), bit-exact),
//       1 = g1==h1==0, 2 = general.
template<int MODE>
__device__ __forceinline__ void patch_pair_hist(const float* __restrict__ p,
                                                const float2* __restrict__ gks2,
                                                float* __restrict__ hrow,
                                                float g0, float g1, float g2,
                                                float h0, float h1, float h2,
                                                int li, int lane, bool act)
{
    const int  sls = (li == 0)  ? lane : lane - 1;   // stays within half-warp
    const int  srs = (li == 15) ? lane : lane + 1;
    const bool pl0 = (li == 0), pl15 = (li == 15);

    float2 cur = __ldg((const float2*)p);            // row 0 (8B aligned)
    float2 prv = cur;                                // replicate-pad top

    #pragma unroll 4
    for (int r = 0; r < PS; ++r) {
        const float2 nxt = (r + 1 < PS) ? __ldg((const float2*)(p + (r + 1) * PS)) : cur;
        const float prevY = __shfl_sync(0xffffffffu, cur.y, sls);
        const float nextX = __shfl_sync(0xffffffffu, cur.x, srs);
        const float lftx = pl0  ? cur.x : prevY;     // left of col 2li (edge pad)
        const float rgty = pl15 ? cur.y : nextX;     // right of col 2li+1

        float gxa, gya, gxb, gyb;
        if (MODE == 0) {
            // g2==-g0, g0=+/-2^k: fadd(g0*l, g2*r) == g0*fsub(l,r) bit-exactly
            gxa = __fmul_rn(g0, __fsub_rn(lftx,  cur.y));
            gya = __fmul_rn(h0, __fsub_rn(prv.x, nxt.x));
            gxb = __fmul_rn(g0, __fsub_rn(cur.x, rgty));
            gyb = __fmul_rn(h0, __fsub_rn(prv.y, nxt.y));
        } else if (MODE == 1) {                      // g1==h1==0 (bit-equal, R6/R7)
            gxa = __fadd_rn(__fmul_rn(g0, lftx),  __fmul_rn(g2, cur.y));
            gya = __fadd_rn(__fmul_rn(h0, prv.x), __fmul_rn(h2, nxt.x));
            gxb = __fadd_rn(__fmul_rn(g0, cur.x), __fmul_rn(g2, rgty));
            gyb = __fadd_rn(__fmul_rn(h0, prv.y), __fmul_rn(h2, nxt.y));
        } else {
            gxa = __fadd_rn(__fadd_rn(__fmul_rn(g0, lftx),  __fmul_rn(g1, cur.x)), __fmul_rn(g2, cur.y));
            gya = __fadd_rn(__fadd_rn(__fmul_rn(h0, prv.x), __fmul_rn(h1, cur.x)), __fmul_rn(h2, nxt.x));
            gxb = __fadd_rn(__fadd_rn(__fmul_rn(g0, cur.x), __fmul_rn(g1, cur.y)), __fmul_rn(g2, rgty));
            gyb = __fadd_rn(__fadd_rn(__fmul_rn(h0, prv.y), __fmul_rn(h1, cur.y)), __fmul_rn(h2, nxt.y));
        }

        const float2 gkv = gks2[r * 16 + li];
        PixOut a = pixel_fast(gxa, gya, gkv.x);
        PixOut b = pixel_fast(gxb, gyb, gkv.y);

        // rare exact fallback, warp-uniform entry (~1.3% of rows)
        if (__any_sync(0xffffffffu, a.nb || b.nb)) {
            if (a.nb) pixel_exact(gxa, gya, gkv.x, a.bin, a.wt);
            if (b.nb) pixel_exact(gxb, gyb, gkv.y, b.bin, b.wt);
        }

        if (act & a.valid) atomicAdd(hrow + a.bin, a.wt);
        if (act & b.valid) atomicAdd(hrow + b.bin, b.wt);

        prv = cur; cur = nxt;
    }
}

__device__ __forceinline__ bool is_pow2_mag(float v) {
    const unsigned u = __float_as_uint(v) & 0x7FFFFFFFu;
    return u != 0u && u < 0x7F800000u && (u & 0x007FFFFFu) == 0u;
}

__global__ void __launch_bounds__(THREADS, 7)     // cap regs ~36 -> high occ
orientation_kernel(const float* __restrict__ x,
                   const float* __restrict__ gxw,
                   const float* __restrict__ gyw,
                   const float* __restrict__ smw,
                   const float* __restrict__ gk,
                   float* __restrict__ out,
                   int B)
{
    __shared__ float2 gks2[PS * PS / 2];
    __shared__ float  hist[WPC * PPW][NBINS];

    const int tid  = threadIdx.x;
    const int lane = tid & 31;
    const int w    = tid >> 5;
    const int h    = lane >> 4;            // half-warp -> which of 2 patches
    const int li   = lane & 15;            // covers columns 2li, 2li+1

    for (int i = tid; i < PS * PS / 2; i += THREADS)
        gks2[i] = ((const float2*)gk)[i];
    for (int i = tid; i < WPC * PPW * NBINS; i += THREADS)
        ((float*)hist)[i] = 0.0f;
    __syncthreads();

    const int patch = (blockIdx.x * WPC + w) * PPW + h;
    const bool act  = patch < B;

    const float g0 = __ldg(gxw + 0), g1 = __ldg(gxw + 1), g2 = __ldg(gxw + 2);
    const float h0 = __ldg(gyw + 0), h1 = __ldg(gyw + 1), h2 = __ldg(gyw + 2);

    const float* p = x + (act ? (size_t)patch * (PS * PS) : 0) + 2 * li;
    float* hrow = hist[w * PPW + h];

    const bool simple = (g1 == 0.0f) && (h1 == 0.0f);
    const bool anti = simple
        && (__float_as_uint(g0) == (__float_as_uint(g2) ^ 0x80000000u))
        && (__float_as_uint(h0) == (__float_as_uint(h2) ^ 0x80000000u))
        && is_pow2_mag(g0) && is_pow2_mag(h0);

    if (anti)
        patch_pair_hist<0>(p, gks2, hrow, g0, g1, g2, h0, h1, h2, li, lane, act);
    else if (simple)
        patch_pair_hist<1>(p, gks2, hrow, g0, g1, g2, h0, h1, h2, li, lane, act);
    else
        patch_pair_hist<2>(p, gks2, hrow, g0, g1, g2, h0, h1, h2, li, lane, act);

    __syncwarp();   // warp w wrote only hists 2w and 2w+1

    // ---- smoothing (zero-pad conv3) + first-index argmax, once per patch ----
    const float s0 = __ldg(smw + 0), s1 = __ldg(smw + 1), s2 = __ldg(smw + 2);
    // hist/(H*W) skipped: exact power-of-2 scale, argmax-invariant.

    #pragma unroll
    for (int j = 0; j < PPW; ++j) {
        const float* hr = hist[w * PPW + j];

        const float a1 = (lane > 0) ? hr[lane - 1] : 0.0f;
        const float m1 = hr[lane];
        const float c1 = hr[lane + 1];               // lane 31 -> bin 32, valid
        float v1 = __fadd_rn(__fadd_rn(__fmul_rn(s0, a1), __fmul_rn(s1, m1)),
                             __fmul_rn(s2, c1));

        float v2 = -1.0f;                            // hist >= 0, never wins
        if (lane < 4) {
            const int b = lane + 32;
            const float a2 = hr[b - 1];
            const float m2v = hr[b];
            const float c2 = (b < NBINS - 1) ? hr[b + 1] : 0.0f;
            v2 = __fadd_rn(__fadd_rn(__fmul_rn(s0, a2), __fmul_rn(s1, m2v)),
                           __fmul_rn(s2, c2));
        }

        float bv; int bi;
        if (v2 > v1) { bv = v2; bi = lane + 32; }
        else         { bv = v1; bi = lane; }

        #pragma unroll
        for (int off = 16; off > 0; off >>= 1) {
            const float ov = __shfl_xor_sync(0xffffffffu, bv, off);
            const int   oi = __shfl_xor_sync(0xffffffffu, bi, off);
            if (ov > bv || (ov == bv && oi < bi)) { bv = ov; bi = oi; }
        }

        const int op = (blockIdx.x * WPC + w) * PPW + j;
        if (lane == 0 && op < B) {
            const float t = __fdiv_rn(__fmul_rn(TWO_PI_F, (float)bi), 36.0f);
            out[op] = -__fsub_rn(t, PI_F);
        }
    }
}

extern "C" void kernel_launch(void* const* d_in, const int* in_sizes, int n_in,
                              void* d_out, int out_size) {
    const float* x   = (const float*)d_in[0];
    const float* gxw = (const float*)d_in[1];
    const float* gyw = (const float*)d_in[2];
    const float* smw = (const float*)d_in[3];
    const float* gk  = (const float*)d_in[4];
    float* out = (float*)d_out;
    const int B = out_size;
    const int grid = (B + WPC * PPW - 1) / (WPC * PPW);
    orientation_kernel<<<grid, THREADS>>>(x, gxw, gyw, smw, gk, out, B);
}

// round 13
// speedup vs baseline: 1.8930x; 1.0573x over previous
#include <cuda_runtime.h>
#include <cuda_bf16.h>

#define NBINS 36
#define PS 32
#define WPC 8                  // warps per CTA; each warp handles 2 patches
#define THREADS (WPC * 32)
#define PPW 2                  // patches per warp
#define HCOPIES 2              // histogram copies per patch (conflict relief)

#define TWO_PI_F 6.28318530717958647692f
#define PI_F     3.14159265358979323846f
#define TAN_PI8  0.4142135623730950488f

// Cephes atanf coefficients pre-multiplied by K = 36/(2*pi) (validated R12).
#define KC9  0.46144556f
#define KC7 -0.79513296f
#define KC5  1.14463840f
#define KC3 -1.90983720f
#define KC1  5.72957795f

struct PixOut { int bin; float wt; bool valid; bool nb; };

// Fast path (R12-validated numerics, unchanged).
__device__ __forceinline__ PixOut pixel_fast(float gx, float gy, float gkv)
{
    PixOut o;
    const float m2 = fmaf(gx, gx, fmaf(gy, gy, 1e-10f));
    float rt;
    asm("sqrt.approx.f32 %0, %1;" : "=f"(rt) : "f"(m2));
    const float mag = rt * gkv;
    o.valid = mag > 0.001f;

    const float ax = fabsf(gx), ay = fabsf(gy);
    const float mn = fminf(ax, ay), mx = fmaxf(ax, ay);
    const bool  red = mn > TAN_PI8 * mx;            // mn/mx > tan(pi/8)
    const float num = red ? (mn - mx) : mn;         // Cephes (rt-1)/(rt+1) folded
    const float den = red ? (mn + mx) : mx;
    const float z   = __fdividef(num, den);         // |z| <= tan(pi/8)
    const float s   = z * z;
    float t = fmaf(KC9, s, KC7);
    t = fmaf(t, s, KC5);
    t = fmaf(t, s, KC3);
    t = fmaf(t, s, KC1);                            // t ~= K*atan(z)/z
    float aU = fmaf(t, z, red ? 4.5f : 0.0f);       // K*atan(mn/mx) in [0, 4.5]
    if (ay > ax)   aU = 9.0f  - aU;                 // K*pi/2
    if (gx < 0.0f) aU = 18.0f - aU;                 // K*pi
    const float ob = (gy < 0.0f) ? 36.0f - aU : aU; // K*2pi

    const float bf = floorf(ob);
    const float fr = ob - bf;
    o.bin = (int)bf;                                // in [0,35] whenever fr>=1e-4
    o.wt  = fmaf(-fr, mag, mag);                    // (1-fr)*mag up to 1 ulp
    o.nb  = fabsf(fr - 0.5f) > 0.4999f;             // window 1e-4 per side
    return o;
}

// Bit-exact reference path (atan2f + rn ops), used for rare boundary pixels.
__device__ __forceinline__ void pixel_exact(float gx, float gy, float gkv,
                                            int& bin, float& wt)
{
    const float m2s  = __fadd_rn(__fadd_rn(__fmul_rn(gx, gx), __fmul_rn(gy, gy)), 1e-10f);
    const float mags = __fmul_rn(__fsqrt_rn(m2s), gkv);
    const float ori  = atan2f(gy, gx);
    const float rr   = (ori < 0.0f) ? __fadd_rn(ori, TWO_PI_F) : ori;
    const float obe  = __fdiv_rn(__fmul_rn(36.0f, rr), TWO_PI_F);
    const float bfe  = floorf(obe);
    const float wo1  = __fsub_rn(obe, bfe);
    wt  = __fmul_rn(__fsub_rn(1.0f, wo1), mags);
    bin = (int)bfe;
    if (bin >= NBINS) bin -= NBINS;
}

// MODE: 0 = antisymmetric power-of-2 weights, 1 = g1==h1==0, 2 = general.
template<int MODE>
__device__ __forceinline__ void patch_pair_hist(const float* __restrict__ p,
                                                const float2* __restrict__ gks2,
                                                float* __restrict__ hrow,
                                                float g0, float g1, float g2,
                                                float h0, float h1, float h2,
                                                int li, int lane, bool act)
{
    const int  sls = (li == 0)  ? lane : lane - 1;   // stays within half-warp
    const int  srs = (li == 15) ? lane : lane + 1;
    const bool pl0 = (li == 0), pl15 = (li == 15);

    float2 cur = __ldg((const float2*)p);            // row 0
    float2 prv = cur;                                // replicate-pad top
    float2 nxt = __ldg((const float2*)(p + PS));     // row 1 (PS>=2)

    #pragma unroll 4
    for (int r = 0; r < PS; ++r) {
        // prefetch row r+2 a full iteration ahead (pad: reuse nxt == row r+1)
        const float2 nxt2 = (r + 2 < PS) ? __ldg((const float2*)(p + (r + 2) * PS)) : nxt;

        const float prevY = __shfl_sync(0xffffffffu, cur.y, sls);
        const float nextX = __shfl_sync(0xffffffffu, cur.x, srs);
        const float lftx = pl0  ? cur.x : prevY;     // left of col 2li (edge pad)
        const float rgty = pl15 ? cur.y : nextX;     // right of col 2li+1

        float gxa, gya, gxb, gyb;
        if (MODE == 0) {
            // g2==-g0, g0=+/-2^k: fadd(g0*l, g2*r) == g0*fsub(l,r) bit-exactly
            gxa = __fmul_rn(g0, __fsub_rn(lftx,  cur.y));
            gya = __fmul_rn(h0, __fsub_rn(prv.x, nxt.x));
            gxb = __fmul_rn(g0, __fsub_rn(cur.x, rgty));
            gyb = __fmul_rn(h0, __fsub_rn(prv.y, nxt.y));
        } else if (MODE == 1) {                      // g1==h1==0
            gxa = __fadd_rn(__fmul_rn(g0, lftx),  __fmul_rn(g2, cur.y));
            gya = __fadd_rn(__fmul_rn(h0, prv.x), __fmul_rn(h2, nxt.x));
            gxb = __fadd_rn(__fmul_rn(g0, cur.x), __fmul_rn(g2, rgty));
            gyb = __fadd_rn(__fmul_rn(h0, prv.y), __fmul_rn(h2, nxt.y));
        } else {
            gxa = __fadd_rn(__fadd_rn(__fmul_rn(g0, lftx),  __fmul_rn(g1, cur.x)), __fmul_rn(g2, cur.y));
            gya = __fadd_rn(__fadd_rn(__fmul_rn(h0, prv.x), __fmul_rn(h1, cur.x)), __fmul_rn(h2, nxt.x));
            gxb = __fadd_rn(__fadd_rn(__fmul_rn(g0, cur.x), __fmul_rn(g1, cur.y)), __fmul_rn(g2, rgty));
            gyb = __fadd_rn(__fadd_rn(__fmul_rn(h0, prv.y), __fmul_rn(h1, cur.y)), __fmul_rn(h2, nxt.y));
        }

        const float2 gkv = gks2[r * 16 + li];
        PixOut a = pixel_fast(gxa, gya, gkv.x);
        PixOut b = pixel_fast(gxb, gyb, gkv.y);

        // rare exact fallback, warp-uniform entry (~1.3% of rows)
        if (__any_sync(0xffffffffu, a.nb || b.nb)) {
            if (a.nb) pixel_exact(gxa, gya, gkv.x, a.bin, a.wt);
            if (b.nb) pixel_exact(gxb, gyb, gkv.y, b.bin, b.wt);
        }

        if (act & a.valid) atomicAdd(hrow + a.bin, a.wt);
        if (act & b.valid) atomicAdd(hrow + b.bin, b.wt);

        prv = cur; cur = nxt; nxt = nxt2;
    }
}

__device__ __forceinline__ bool is_pow2_mag(float v) {
    const unsigned u = __float_as_uint(v) & 0x7FFFFFFFu;
    return u != 0u && u < 0x7F800000u && (u & 0x007FFFFFu) == 0u;
}

__global__ void __launch_bounds__(THREADS, 7)     // cap regs ~36 -> high occ
orientation_kernel(const float* __restrict__ x,
                   const float* __restrict__ gxw,
                   const float* __restrict__ gyw,
                   const float* __restrict__ smw,
                   const float* __restrict__ gk,
                   float* __restrict__ out,
                   int B)
{
    __shared__ float2 gks2[PS * PS / 2];
    __shared__ float  hist[WPC * PPW * HCOPIES][NBINS];

    const int tid  = threadIdx.x;
    const int lane = tid & 31;
    const int w    = tid >> 5;
    const int h    = lane >> 4;            // half-warp -> which of 2 patches
    const int li   = lane & 15;            // covers columns 2li, 2li+1

    for (int i = tid; i < PS * PS / 2; i += THREADS)
        gks2[i] = ((const float2*)gk)[i];
    for (int i = tid; i < WPC * PPW * HCOPIES * NBINS; i += THREADS)
        ((float*)hist)[i] = 0.0f;
    __syncthreads();

    const int patch = (blockIdx.x * WPC + w) * PPW + h;
    const bool act  = patch < B;

    const float g0 = __ldg(gxw + 0), g1 = __ldg(gxw + 1), g2 = __ldg(gxw + 2);
    const float h0 = __ldg(gyw + 0), h1 = __ldg(gyw + 1), h2 = __ldg(gyw + 2);

    const float* p = x + (act ? (size_t)patch * (PS * PS) : 0) + 2 * li;
    // even li -> copy 0, odd li -> copy 1 (halves atomic conflict degree)
    float* hrow = hist[(w * PPW + h) * HCOPIES + (li & 1)];

    const bool simple = (g1 == 0.0f) && (h1 == 0.0f);
    const bool anti = simple
        && (__float_as_uint(g0) == (__float_as_uint(g2) ^ 0x80000000u))
        && (__float_as_uint(h0) == (__float_as_uint(h2) ^ 0x80000000u))
        && is_pow2_mag(g0) && is_pow2_mag(h0);

    if (anti)
        patch_pair_hist<0>(p, gks2, hrow, g0, g1, g2, h0, h1, h2, li, lane, act);
    else if (simple)
        patch_pair_hist<1>(p, gks2, hrow, g0, g1, g2, h0, h1, h2, li, lane, act);
    else
        patch_pair_hist<2>(p, gks2, hrow, g0, g1, g2, h0, h1, h2, li, lane, act);

    __syncwarp();   // warp w wrote only its own 4 hist rows

    // ---- merge the two copies per patch ----
    #pragma unroll
    for (int j = 0; j < PPW; ++j) {
        float* h0p = hist[(w * PPW + j) * HCOPIES];
        const float* h1p = hist[(w * PPW + j) * HCOPIES + 1];
        h0p[lane] += h1p[lane];
        if (lane < NBINS - 32) h0p[lane + 32] += h1p[lane + 32];
    }
    __syncwarp();

    // ---- smoothing (zero-pad conv3) + first-index argmax, once per patch ----
    const float s0 = __ldg(smw + 0), s1 = __ldg(smw + 1), s2 = __ldg(smw + 2);
    // hist/(H*W) skipped: exact power-of-2 scale, argmax-invariant.

    #pragma unroll
    for (int j = 0; j < PPW; ++j) {
        const float* hr = hist[(w * PPW + j) * HCOPIES];

        const float a1 = (lane > 0) ? hr[lane - 1] : 0.0f;
        const float m1 = hr[lane];
        const float c1 = hr[lane + 1];               // lane 31 -> bin 32, valid
        float v1 = __fadd_rn(__fadd_rn(__fmul_rn(s0, a1), __fmul_rn(s1, m1)),
                             __fmul_rn(s2, c1));

        float v2 = -1.0f;                            // hist >= 0, never wins
        if (lane < 4) {
            const int b = lane + 32;
            const float a2 = hr[b - 1];
            const float m2v = hr[b];
            const float c2 = (b < NBINS - 1) ? hr[b + 1] : 0.0f;
            v2 = __fadd_rn(__fadd_rn(__fmul_rn(s0, a2), __fmul_rn(s1, m2v)),
                           __fmul_rn(s2, c2));
        }

        float bv; int bi;
        if (v2 > v1) { bv = v2; bi = lane + 32; }
        else         { bv = v1; bi = lane; }

        #pragma unroll
        for (int off = 16; off > 0; off >>= 1) {
            const float ov = __shfl_xor_sync(0xffffffffu, bv, off);
            const int   oi = __shfl_xor_sync(0xffffffffu, bi, off);
            if (ov > bv || (ov == bv && oi < bi)) { bv = ov; bi = oi; }
        }

        const int op = (blockIdx.x * WPC + w) * PPW + j;
        if (lane == 0 && op < B) {
            const float t = __fdiv_rn(__fmul_rn(TWO_PI_F, (float)bi), 36.0f);
            out[op] = -__fsub_rn(t, PI_F);
        }
    }
}

extern "C" void kernel_launch(void* const* d_in, const int* in_sizes, int n_in,
                              void* d_out, int out_size) {
    const float* x   = (const float*)d_in[0];
    const float* gxw = (const float*)d_in[1];
    const float* gyw = (const float*)d_in[2];
    const float* smw = (const float*)d_in[3];
    const float* gk  = (const float*)d_in[4];
    float* out = (float*)d_out;
    const int B = out_size;
    const int grid = (B + WPC * PPW - 1) / (WPC * PPW);
    orientation_kernel<<<grid, THREADS>>>(x, gxw, gyw, smw, gk, out, B);
}

// round 15
// speedup vs baseline: 1.9414x; 1.0256x over previous
#include <cuda_runtime.h>
#include <cuda_bf16.h>

#define NBINS 36
#define PS 32
#define WPC 8                  // warps per CTA; each warp handles 2 patches
#define THREADS (WPC * 32)
#define PPW 2                  // patches per warp
#define HCOPIES 4              // histogram copies per patch (conflict relief)

#define TWO_PI_F 6.28318530717958647692f
#define PI_F     3.14159265358979323846f
#define TAN_PI8  0.4142135623730950488f

// Cephes atanf coefficients pre-multiplied by K = 36/(2*pi) (validated R12/R13).
#define KC9  0.46144556f
#define KC7 -0.79513296f
#define KC5  1.14463840f
#define KC3 -1.90983720f
#define KC1  5.72957795f

struct PixOut { int bin; float wt; bool valid; bool nb; };

// Fast path (R12/R13-validated numerics, unchanged).
__device__ __forceinline__ PixOut pixel_fast(float gx, float gy, float gkv)
{
    PixOut o;
    const float m2 = fmaf(gx, gx, fmaf(gy, gy, 1e-10f));
    float rt;
    asm("sqrt.approx.f32 %0, %1;" : "=f"(rt) : "f"(m2));
    const float mag = rt * gkv;
    o.valid = mag > 0.001f;

    const float ax = fabsf(gx), ay = fabsf(gy);
    const float mn = fminf(ax, ay), mx = fmaxf(ax, ay);
    const bool  red = mn > TAN_PI8 * mx;            // mn/mx > tan(pi/8)
    const float num = red ? (mn - mx) : mn;         // Cephes (rt-1)/(rt+1) folded
    const float den = red ? (mn + mx) : mx;
    const float z   = __fdividef(num, den);         // |z| <= tan(pi/8)
    const float s   = z * z;
    float t = fmaf(KC9, s, KC7);
    t = fmaf(t, s, KC5);
    t = fmaf(t, s, KC3);
    t = fmaf(t, s, KC1);                            // t ~= K*atan(z)/z
    float aU = fmaf(t, z, red ? 4.5f : 0.0f);       // K*atan(mn/mx) in [0, 4.5]
    if (ay > ax)   aU = 9.0f  - aU;                 // K*pi/2
    if (gx < 0.0f) aU = 18.0f - aU;                 // K*pi
    const float ob = (gy < 0.0f) ? 36.0f - aU : aU; // K*2pi

    const float bf = floorf(ob);
    const float fr = ob - bf;
    o.bin = (int)bf;                                // in [0,35] whenever fr>=1e-4
    o.wt  = fmaf(-fr, mag, mag);                    // (1-fr)*mag up to 1 ulp
    o.nb  = fabsf(fr - 0.5f) > 0.4999f;             // window 1e-4 per side
    return o;
}

// Bit-exact reference path (atan2f + rn ops), used for rare boundary pixels.
__device__ __forceinline__ void pixel_exact(float gx, float gy, float gkv,
                                            int& bin, float& wt)
{
    const float m2s  = __fadd_rn(__fadd_rn(__fmul_rn(gx, gx), __fmul_rn(gy, gy)), 1e-10f);
    const float mags = __fmul_rn(__fsqrt_rn(m2s), gkv);
    const float ori  = atan2f(gy, gx);
    const float rr   = (ori < 0.0f) ? __fadd_rn(ori, TWO_PI_F) : ori;
    const float obe  = __fdiv_rn(__fmul_rn(36.0f, rr), TWO_PI_F);
    const float bfe  = floorf(obe);
    const float wo1  = __fsub_rn(obe, bfe);
    wt  = __fmul_rn(__fsub_rn(1.0f, wo1), mags);
    bin = (int)bfe;
    if (bin >= NBINS) bin -= NBINS;
}

// MODE: 0 = antisymmetric power-of-2 weights, 1 = g1==h1==0, 2 = general.
template<int MODE>
__device__ __forceinline__ void patch_pair_hist(const float* __restrict__ p,
                                                const float2* __restrict__ gks2,
                                                float* __restrict__ hrow,
                                                float g0, float g1, float g2,
                                                float h0, float h1, float h2,
                                                int li, int lane, bool act)
{
    const int  sls = (li == 0)  ? lane : lane - 1;   // stays within half-warp
    const int  srs = (li == 15) ? lane : lane + 1;
    const bool pl0 = (li == 0), pl15 = (li == 15);

    float2 cur = __ldg((const float2*)p);            // row 0
    float2 prv = cur;                                // replicate-pad top
    float2 nxt = __ldg((const float2*)(p + PS));     // row 1 (PS>=2)
    float2 gkv = gks2[li];                           // row 0 gk

    #pragma unroll 8
    for (int r = 0; r < PS; ++r) {
        // prefetch row r+2 pixels and row r+1 gk a full iteration ahead
        const float2 nxt2 = (r + 2 < PS) ? __ldg((const float2*)(p + (r + 2) * PS)) : nxt;
        const float2 gkv2 = (r + 1 < PS) ? gks2[(r + 1) * 16 + li] : gkv;

        const float prevY = __shfl_sync(0xffffffffu, cur.y, sls);
        const float nextX = __shfl_sync(0xffffffffu, cur.x, srs);
        const float lftx = pl0  ? cur.x : prevY;     // left of col 2li (edge pad)
        const float rgty = pl15 ? cur.y : nextX;     // right of col 2li+1

        float gxa, gya, gxb, gyb;
        if (MODE == 0) {
            // g2==-g0, g0=+/-2^k: fadd(g0*l, g2*r) == g0*fsub(l,r) bit-exactly
            gxa = __fmul_rn(g0, __fsub_rn(lftx,  cur.y));
            gya = __fmul_rn(h0, __fsub_rn(prv.x, nxt.x));
            gxb = __fmul_rn(g0, __fsub_rn(cur.x, rgty));
            gyb = __fmul_rn(h0, __fsub_rn(prv.y, nxt.y));
        } else if (MODE == 1) {                      // g1==h1==0
            gxa = __fadd_rn(__fmul_rn(g0, lftx),  __fmul_rn(g2, cur.y));
            gya = __fadd_rn(__fmul_rn(h0, prv.x), __fmul_rn(h2, nxt.x));
            gxb = __fadd_rn(__fmul_rn(g0, cur.x), __fmul_rn(g2, rgty));
            gyb = __fadd_rn(__fmul_rn(h0, prv.y), __fmul_rn(h2, nxt.y));
        } else {
            gxa = __fadd_rn(__fadd_rn(__fmul_rn(g0, lftx),  __fmul_rn(g1, cur.x)), __fmul_rn(g2, cur.y));
            gya = __fadd_rn(__fadd_rn(__fmul_rn(h0, prv.x), __fmul_rn(h1, cur.x)), __fmul_rn(h2, nxt.x));
            gxb = __fadd_rn(__fadd_rn(__fmul_rn(g0, cur.x), __fmul_rn(g1, cur.y)), __fmul_rn(g2, rgty));
            gyb = __fadd_rn(__fadd_rn(__fmul_rn(h0, prv.y), __fmul_rn(h1, cur.y)), __fmul_rn(h2, nxt.y));
        }

        PixOut a = pixel_fast(gxa, gya, gkv.x);
        PixOut b = pixel_fast(gxb, gyb, gkv.y);

        // rare exact fallback, warp-uniform entry (~1.3% of rows)
        if (__any_sync(0xffffffffu, a.nb || b.nb)) {
            if (a.nb) pixel_exact(gxa, gya, gkv.x, a.bin, a.wt);
            if (b.nb) pixel_exact(gxb, gyb, gkv.y, b.bin, b.wt);
        }

        if (act & a.valid) atomicAdd(hrow + a.bin, a.wt);
        if (act & b.valid) atomicAdd(hrow + b.bin, b.wt);

        prv = cur; cur = nxt; nxt = nxt2; gkv = gkv2;
    }
}

__device__ __forceinline__ bool is_pow2_mag(float v) {
    const unsigned u = __float_as_uint(v) & 0x7FFFFFFFu;
    return u != 0u && u < 0x7F800000u && (u & 0x007FFFFFu) == 0u;
}

__global__ void __launch_bounds__(THREADS, 7)     // cap regs ~36 -> high occ
orientation_kernel(const float* __restrict__ x,
                   const float* __restrict__ gxw,
                   const float* __restrict__ gyw,
                   const float* __restrict__ smw,
                   const float* __restrict__ gk,
                   float* __restrict__ out,
                   int B)
{
    __shared__ float2 gks2[PS * PS / 2];
    __shared__ float  hist[WPC * PPW * HCOPIES][NBINS];

    const int tid  = threadIdx.x;
    const int lane = tid & 31;
    const int w    = tid >> 5;
    const int h    = lane >> 4;            // half-warp -> which of 2 patches
    const int li   = lane & 15;            // covers columns 2li, 2li+1

    for (int i = tid; i < PS * PS / 2; i += THREADS)
        gks2[i] = ((const float2*)gk)[i];
    for (int i = tid; i < WPC * PPW * HCOPIES * NBINS; i += THREADS)
        ((float*)hist)[i] = 0.0f;
    __syncthreads();

    const int patch = (blockIdx.x * WPC + w) * PPW + h;
    const bool act  = patch < B;

    const float g0 = __ldg(gxw + 0), g1 = __ldg(gxw + 1), g2 = __ldg(gxw + 2);
    const float h0 = __ldg(gyw + 0), h1 = __ldg(gyw + 1), h2 = __ldg(gyw + 2);

    const float* p = x + (act ? (size_t)patch * (PS * PS) : 0) + 2 * li;
    // li&3 -> one of 4 copies (quarters atomic conflict degree)
    float* hrow = hist[(w * PPW + h) * HCOPIES + (li & 3)];

    const bool simple = (g1 == 0.0f) && (h1 == 0.0f);
    const bool anti = simple
        && (__float_as_uint(g0) == (__float_as_uint(g2) ^ 0x80000000u))
        && (__float_as_uint(h0) == (__float_as_uint(h2) ^ 0x80000000u))
        && is_pow2_mag(g0) && is_pow2_mag(h0);

    if (anti)
        patch_pair_hist<0>(p, gks2, hrow, g0, g1, g2, h0, h1, h2, li, lane, act);
    else if (simple)
        patch_pair_hist<1>(p, gks2, hrow, g0, g1, g2, h0, h1, h2, li, lane, act);
    else
        patch_pair_hist<2>(p, gks2, hrow, g0, g1, g2, h0, h1, h2, li, lane, act);

    __syncwarp();   // warp w wrote only its own hist rows

    // ---- merge the HCOPIES copies per patch into copy 0 ----
    #pragma unroll
    for (int j = 0; j < PPW; ++j) {
        float* hb = hist[(w * PPW + j) * HCOPIES];   // copies at +c*NBINS
        float v = hb[lane] + hb[lane + NBINS] + hb[lane + 2 * NBINS] + hb[lane + 3 * NBINS];
        hb[lane] = v;
        if (lane < NBINS - 32) {
            const int b = lane + 32;
            float v2 = hb[b] + hb[b + NBINS] + hb[b + 2 * NBINS] + hb[b + 3 * NBINS];
            hb[b] = v2;
        }
    }
    __syncwarp();

    // ---- smoothing (zero-pad conv3) + first-index argmax, once per patch ----
    const float s0 = __ldg(smw + 0), s1 = __ldg(smw + 1), s2 = __ldg(smw + 2);
    // hist/(H*W) skipped: exact power-of-2 scale, argmax-invariant.

    #pragma unroll
    for (int j = 0; j < PPW; ++j) {
        const float* hr = hist[(w * PPW + j) * HCOPIES];

        const float a1 = (lane > 0) ? hr[lane - 1] : 0.0f;
        const float m1 = hr[lane];
        const float c1 = hr[lane + 1];               // lane 31 -> bin 32, valid
        float v1 = __fadd_rn(__fadd_rn(__fmul_rn(s0, a1), __fmul_rn(s1, m1)),
                             __fmul_rn(s2, c1));

        float v2 = -1.0f;                            // hist >= 0, never wins
        if (lane < 4) {
            const int b = lane + 32;
            const float a2 = hr[b - 1];
            const float m2v = hr[b];
            const float c2 = (b < NBINS - 1) ? hr[b + 1] : 0.0f;
            v2 = __fadd_rn(__fadd_rn(__fmul_rn(s0, a2), __fmul_rn(s1, m2v)),
                           __fmul_rn(s2, c2));
        }

        float bv; int bi;
        if (v2 > v1) { bv = v2; bi = lane + 32; }
        else         { bv = v1; bi = lane; }

        #pragma unroll
        for (int off = 16; off > 0; off >>= 1) {
            const float ov = __shfl_xor_sync(0xffffffffu, bv, off);
            const int   oi = __shfl_xor_sync(0xffffffffu, bi, off);
            if (ov > bv || (ov == bv && oi < bi)) { bv = ov; bi = oi; }
        }

        const int op = (blockIdx.x * WPC + w) * PPW + j;
        if (lane == 0 && op < B) {
            const float t = __fdiv_rn(__fmul_rn(TWO_PI_F, (float)bi), 36.0f);
            out[op] = -__fsub_rn(t, PI_F);
        }
    }
}

extern "C" void kernel_launch(void* const* d_in, const int* in_sizes, int n_in,
                              void* d_out, int out_size) {
    const float* x   = (const float*)d_in[0];
    const float* gxw = (const float*)d_in[1];
    const float* gyw = (const float*)d_in[2];
    const float* smw = (const float*)d_in[3];
    const float* gk  = (const float*)d_in[4];
    float* out = (float*)d_out;
    const int B = out_size;
    const int grid = (B + WPC * PPW - 1) / (WPC * PPW);
    orientation_kernel<<<grid, THREADS>>>(x, gxw, gyw, smw, gk, out, B);
}

// round 16
// speedup vs baseline: 1.9501x; 1.0045x over previous
#include <cuda_runtime.h>
#include <cuda_bf16.h>

#define NBINS 36
#define PS 32
#define WPC 8                  // warps per CTA; each warp handles 2 patches
#define THREADS (WPC * 32)
#define PPW 2                  // patches per warp
#define HCOPIES 8              // histogram copies per patch (conflict relief)

#define TWO_PI_F 6.28318530717958647692f
#define PI_F     3.14159265358979323846f
#define TAN_PI8  0.4142135623730950488f

// Cephes atanf coefficients pre-multiplied by K = 36/(2*pi) (validated R12-R15).
#define KC9  0.46144556f
#define KC7 -0.79513296f
#define KC5  1.14463840f
#define KC3 -1.90983720f
#define KC1  5.72957795f

struct PixOut { int bin; float wt; bool valid; bool nb; };

// Fast path (R12-R15-validated numerics, unchanged).
__device__ __forceinline__ PixOut pixel_fast(float gx, float gy, float gkv)
{
    PixOut o;
    const float m2 = fmaf(gx, gx, fmaf(gy, gy, 1e-10f));
    float rt;
    asm("sqrt.approx.f32 %0, %1;" : "=f"(rt) : "f"(m2));
    const float mag = rt * gkv;
    o.valid = mag > 0.001f;

    const float ax = fabsf(gx), ay = fabsf(gy);
    const float mn = fminf(ax, ay), mx = fmaxf(ax, ay);
    const bool  red = mn > TAN_PI8 * mx;            // mn/mx > tan(pi/8)
    const float num = red ? (mn - mx) : mn;         // Cephes (rt-1)/(rt+1) folded
    const float den = red ? (mn + mx) : mx;
    const float z   = __fdividef(num, den);         // |z| <= tan(pi/8)
    const float s   = z * z;
    float t = fmaf(KC9, s, KC7);
    t = fmaf(t, s, KC5);
    t = fmaf(t, s, KC3);
    t = fmaf(t, s, KC1);                            // t ~= K*atan(z)/z
    float aU = fmaf(t, z, red ? 4.5f : 0.0f);       // K*atan(mn/mx) in [0, 4.5]
    if (ay > ax)   aU = 9.0f  - aU;                 // K*pi/2
    if (gx < 0.0f) aU = 18.0f - aU;                 // K*pi
    const float ob = (gy < 0.0f) ? 36.0f - aU : aU; // K*2pi

    const float bf = floorf(ob);
    const float fr = ob - bf;
    o.bin = (int)bf;                                // in [0,35] whenever fr>=1e-4
    o.wt  = fmaf(-fr, mag, mag);                    // (1-fr)*mag up to 1 ulp
    o.nb  = fabsf(fr - 0.5f) > 0.4999f;             // window 1e-4 per side
    return o;
}

// Bit-exact reference path (atan2f + rn ops), used for rare boundary pixels.
__device__ __forceinline__ void pixel_exact(float gx, float gy, float gkv,
                                            int& bin, float& wt)
{
    const float m2s  = __fadd_rn(__fadd_rn(__fmul_rn(gx, gx), __fmul_rn(gy, gy)), 1e-10f);
    const float mags = __fmul_rn(__fsqrt_rn(m2s), gkv);
    const float ori  = atan2f(gy, gx);
    const float rr   = (ori < 0.0f) ? __fadd_rn(ori, TWO_PI_F) : ori;
    const float obe  = __fdiv_rn(__fmul_rn(36.0f, rr), TWO_PI_F);
    const float bfe  = floorf(obe);
    const float wo1  = __fsub_rn(obe, bfe);
    wt  = __fmul_rn(__fsub_rn(1.0f, wo1), mags);
    bin = (int)bfe;
    if (bin >= NBINS) bin -= NBINS;
}

// One row of both pixels: shuffles, gradients, fast path, rare fallback, atomics.
template<int MODE>
__device__ __forceinline__ void row_body(float2 prv, float2 cur, float2 nxt,
                                         float2 gkv,
                                         float g0, float g1, float g2,
                                         float h0, float h1, float h2,
                                         float* __restrict__ hrow, bool act,
                                         int sls, int srs, bool pl0, bool pl15)
{
    const float prevY = __shfl_sync(0xffffffffu, cur.y, sls);
    const float nextX = __shfl_sync(0xffffffffu, cur.x, srs);
    const float lftx = pl0  ? cur.x : prevY;     // left of col 2li (edge pad)
    const float rgty = pl15 ? cur.y : nextX;     // right of col 2li+1

    float gxa, gya, gxb, gyb;
    if (MODE == 0) {
        // g2==-g0, g0=+/-2^k: fadd(g0*l, g2*r) == g0*fsub(l,r) bit-exactly
        gxa = __fmul_rn(g0, __fsub_rn(lftx,  cur.y));
        gya = __fmul_rn(h0, __fsub_rn(prv.x, nxt.x));
        gxb = __fmul_rn(g0, __fsub_rn(cur.x, rgty));
        gyb = __fmul_rn(h0, __fsub_rn(prv.y, nxt.y));
    } else if (MODE == 1) {                      // g1==h1==0
        gxa = __fadd_rn(__fmul_rn(g0, lftx),  __fmul_rn(g2, cur.y));
        gya = __fadd_rn(__fmul_rn(h0, prv.x), __fmul_rn(h2, nxt.x));
        gxb = __fadd_rn(__fmul_rn(g0, cur.x), __fmul_rn(g2, rgty));
        gyb = __fadd_rn(__fmul_rn(h0, prv.y), __fmul_rn(h2, nxt.y));
    } else {
        gxa = __fadd_rn(__fadd_rn(__fmul_rn(g0, lftx),  __fmul_rn(g1, cur.x)), __fmul_rn(g2, cur.y));
        gya = __fadd_rn(__fadd_rn(__fmul_rn(h0, prv.x), __fmul_rn(h1, cur.x)), __fmul_rn(h2, nxt.x));
        gxb = __fadd_rn(__fadd_rn(__fmul_rn(g0, cur.x), __fmul_rn(g1, cur.y)), __fmul_rn(g2, rgty));
        gyb = __fadd_rn(__fadd_rn(__fmul_rn(h0, prv.y), __fmul_rn(h1, cur.y)), __fmul_rn(h2, nxt.y));
    }

    PixOut a = pixel_fast(gxa, gya, gkv.x);
    PixOut b = pixel_fast(gxb, gyb, gkv.y);

    // rare exact fallback, warp-uniform entry (~1.3% of rows)
    if (__any_sync(0xffffffffu, a.nb || b.nb)) {
        if (a.nb) pixel_exact(gxa, gya, gkv.x, a.bin, a.wt);
        if (b.nb) pixel_exact(gxb, gyb, gkv.y, b.bin, b.wt);
    }

    if (act & a.valid) atomicAdd(hrow + a.bin, a.wt);
    if (act & b.valid) atomicAdd(hrow + b.bin, b.wt);
}

template<int MODE>
__device__ __forceinline__ void patch_pair_hist(const float* __restrict__ p,
                                                const float2* __restrict__ gks2,
                                                float* __restrict__ hrow,
                                                float g0, float g1, float g2,
                                                float h0, float h1, float h2,
                                                int li, bool act, int lane)
{
    const int  sls = (li == 0)  ? lane : lane - 1;   // stays within half-warp
    const int  srs = (li == 15) ? lane : lane + 1;
    const bool pl0 = (li == 0), pl15 = (li == 15);

    float2 cur = __ldg((const float2*)p);            // row 0
    float2 prv = cur;                                // replicate-pad top
    float2 nxt = __ldg((const float2*)(p + PS));     // row 1
    float2 gkv = gks2[li];                           // row 0 gk

    // Row-0 skip: if gk row 0 is all zeros (true for the circular mask), row 0
    // contributes nothing (mag==0 -> no atomic) -- skip its whole body.
    int rs = 0;
    if (__all_sync(0xffffffffu, (gkv.x == 0.0f) && (gkv.y == 0.0f))) {
        prv = cur; cur = nxt;
        nxt = __ldg((const float2*)(p + 2 * PS));
        gkv = gks2[16 + li];
        rs = 1;
    }

    // main loop: r in [rs, PS-3], prefetch row r+2 / gk r+1 unconditionally
    #pragma unroll 4
    for (int r = rs; r < PS - 2; ++r) {
        const float2 nxt2 = __ldg((const float2*)(p + (r + 2) * PS));
        const float2 gkv2 = gks2[(r + 1) * 16 + li];
        row_body<MODE>(prv, cur, nxt, gkv, g0, g1, g2, h0, h1, h2,
                       hrow, act, sls, srs, pl0, pl15);
        prv = cur; cur = nxt; nxt = nxt2; gkv = gkv2;
    }
    // r = PS-2 (30): no row r+2 to prefetch
    {
        const float2 gkv2 = gks2[(PS - 1) * 16 + li];
        row_body<MODE>(prv, cur, nxt, gkv, g0, g1, g2, h0, h1, h2,
                       hrow, act, sls, srs, pl0, pl15);
        prv = cur; cur = nxt; gkv = gkv2;
    }
    // r = PS-1 (31): bottom replicate-pad (nxt = cur)
    row_body<MODE>(prv, cur, cur, gkv, g0, g1, g2, h0, h1, h2,
                   hrow, act, sls, srs, pl0, pl15);
}

__device__ __forceinline__ bool is_pow2_mag(float v) {
    const unsigned u = __float_as_uint(v) & 0x7FFFFFFFu;
    return u != 0u && u < 0x7F800000u && (u & 0x007FFFFFu) == 0u;
}

__global__ void __launch_bounds__(THREADS, 7)     // cap regs ~36 -> high occ
orientation_kernel(const float* __restrict__ x,
                   const float* __restrict__ gxw,
                   const float* __restrict__ gyw,
                   const float* __restrict__ smw,
                   const float* __restrict__ gk,
                   float* __restrict__ out,
                   int B)
{
    __shared__ float2 gks2[PS * PS / 2];
    __shared__ float  hist[WPC * PPW * HCOPIES][NBINS];

    const int tid  = threadIdx.x;
    const int lane = tid & 31;
    const int w    = tid >> 5;
    const int h    = lane >> 4;            // half-warp -> which of 2 patches
    const int li   = lane & 15;            // covers columns 2li, 2li+1

    for (int i = tid; i < PS * PS / 2; i += THREADS)
        gks2[i] = ((const float2*)gk)[i];
    for (int i = tid; i < WPC * PPW * HCOPIES * NBINS; i += THREADS)
        ((float*)hist)[i] = 0.0f;
    __syncthreads();

    const int patch = (blockIdx.x * WPC + w) * PPW + h;
    const bool act  = patch < B;

    const float g0 = __ldg(gxw + 0), g1 = __ldg(gxw + 1), g2 = __ldg(gxw + 2);
    const float h0 = __ldg(gyw + 0), h1 = __ldg(gyw + 1), h2 = __ldg(gyw + 2);

    const float* p = x + (act ? (size_t)patch * (PS * PS) : 0) + 2 * li;
    // li&7 -> one of 8 copies (2 lanes per copy: near conflict-free atomics)
    float* hrow = hist[(w * PPW + h) * HCOPIES + (li & 7)];

    const bool simple = (g1 == 0.0f) && (h1 == 0.0f);
    const bool anti = simple
        && (__float_as_uint(g0) == (__float_as_uint(g2) ^ 0x80000000u))
        && (__float_as_uint(h0) == (__float_as_uint(h2) ^ 0x80000000u))
        && is_pow2_mag(g0) && is_pow2_mag(h0);

    if (anti)
        patch_pair_hist<0>(p, gks2, hrow, g0, g1, g2, h0, h1, h2, li, act, lane);
    else if (simple)
        patch_pair_hist<1>(p, gks2, hrow, g0, g1, g2, h0, h1, h2, li, act, lane);
    else
        patch_pair_hist<2>(p, gks2, hrow, g0, g1, g2, h0, h1, h2, li, act, lane);

    __syncwarp();   // warp w wrote only its own hist rows

    // ---- merge the HCOPIES copies per patch into copy 0 ----
    #pragma unroll
    for (int j = 0; j < PPW; ++j) {
        float* hb = hist[(w * PPW + j) * HCOPIES];   // copies at +c*NBINS
        float v = hb[lane];
        #pragma unroll
        for (int c = 1; c < HCOPIES; ++c) v += hb[lane + c * NBINS];
        hb[lane] = v;
        if (lane < NBINS - 32) {
            const int b = lane + 32;
            float v2 = hb[b];
            #pragma unroll
            for (int c = 1; c < HCOPIES; ++c) v2 += hb[b + c * NBINS];
            hb[b] = v2;
        }
    }
    __syncwarp();

    // ---- smoothing (zero-pad conv3) + first-index argmax, once per patch ----
    const float s0 = __ldg(smw + 0), s1 = __ldg(smw + 1), s2 = __ldg(smw + 2);
    // hist/(H*W) skipped: exact power-of-2 scale, argmax-invariant.

    #pragma unroll
    for (int j = 0; j < PPW; ++j) {
        const float* hr = hist[(w * PPW + j) * HCOPIES];

        const float a1 = (lane > 0) ? hr[lane - 1] : 0.0f;
        const float m1 = hr[lane];
        const float c1 = hr[lane + 1];               // lane 31 -> bin 32, valid
        float v1 = __fadd_rn(__fadd_rn(__fmul_rn(s0, a1), __fmul_rn(s1, m1)),
                             __fmul_rn(s2, c1));

        float v2 = -1.0f;                            // hist >= 0, never wins
        if (lane < 4) {
            const int b = lane + 32;
            const float a2 = hr[b - 1];
            const float m2v = hr[b];
            const float c2 = (b < NBINS - 1) ? hr[b + 1] : 0.0f;
            v2 = __fadd_rn(__fadd_rn(__fmul_rn(s0, a2), __fmul_rn(s1, m2v)),
                           __fmul_rn(s2, c2));
        }

        float bv; int bi;
        if (v2 > v1) { bv = v2; bi = lane + 32; }
        else         { bv = v1; bi = lane; }

        #pragma unroll
        for (int off = 16; off > 0; off >>= 1) {
            const float ov = __shfl_xor_sync(0xffffffffu, bv, off);
            const int   oi = __shfl_xor_sync(0xffffffffu, bi, off);
            if (ov > bv || (ov == bv && oi < bi)) { bv = ov; bi = oi; }
        }

        const int op = (blockIdx.x * WPC + w) * PPW + j;
        if (lane == 0 && op < B) {
            const float t = __fdiv_rn(__fmul_rn(TWO_PI_F, (float)bi), 36.0f);
            out[op] = -__fsub_rn(t, PI_F);
        }
    }
}

extern "C" void kernel_launch(void* const* d_in, const int* in_sizes, int n_in,
                              void* d_out, int out_size) {
    const float* x   = (const float*)d_in[0];
    const float* gxw = (const float*)d_in[1];
    const float* gyw = (const float*)d_in[2];
    const float* smw = (const float*)d_in[3];
    const float* gk  = (const float*)d_in[4];
    float* out = (float*)d_out;
    const int B = out_size;
    const int grid = (B + WPC * PPW - 1) / (WPC * PPW);
    orientation_kernel<<<grid, THREADS>>>(x, gxw, gyw, smw, gk, out, B);
}